// round 7
// baseline (speedup 1.0000x reference)
#include <cuda_runtime.h>
#include <math.h>

#define NDIM 8
#define THREADS 256
#define BLOCKS (148 * 7)   // 7 CTAs/SM: smem cap (7 * 32KB = 224KB <= 228KB), occ 87.5%

// u4: [N, 8] fp32 viewed as 2x float4 per point
// grid: [8, ninc+1] row-major
// out layout: x [N,8] then log_jac [N]
__global__ void __launch_bounds__(THREADS)
vegas_map_kernel(const float4* __restrict__ u4,
                 const float*  __restrict__ grid,
                 float4*       __restrict__ x4,
                 float*        __restrict__ logj,
                 int n, int ninc)
{
    const int gw = ninc + 1;
    extern __shared__ float sg[];                       // NDIM * (ninc+1)
    for (int i = threadIdx.x; i < NDIM * gw; i += blockDim.x)
        sg[i] = grid[i];
    __syncthreads();

    const float fninc = (float)ninc;
    const float logC  = (float)NDIM * logf(fninc);      // once per thread

    const int stride = gridDim.x * blockDim.x;
    for (int p = blockIdx.x * blockDim.x + threadIdx.x; p < n; p += stride) {
        float4 a = u4[2 * p];
        float4 b = u4[2 * p + 1];
        float uu[NDIM] = {a.x, a.y, a.z, a.w, b.x, b.y, b.z, b.w};
        float xx[NDIM];
        float prod = 1.0f;

        #pragma unroll
        for (int d = 0; d < NDIM; d++) {
            float t  = uu[d] * fninc;
            int   iu = (int)t;                          // u >= 0: trunc == floor
            float du = t - (float)iu;
            bool  in = (iu < ninc);
            int   ic = in ? iu : (ninc - 1);
            float glo = sg[d * gw + ic];
            float ghi = sg[d * gw + ic + 1];
            float h   = ghi - glo;                      // == inc[d][ic] bit-exactly
            xx[d] = in ? fmaf(h, du, glo) : ghi;        // ghi == grid[d][ninc] when !in
            prod *= h;                                  // ninc factors folded into logC
        }

        x4[2 * p]     = make_float4(xx[0], xx[1], xx[2], xx[3]);
        x4[2 * p + 1] = make_float4(xx[4], xx[5], xx[6], xx[7]);
        logj[p] = __logf(prod) + logC;                  // MUFU LG2, not libm polynomial
    }
}

extern "C" void kernel_launch(void* const* d_in, const int* in_sizes, int n_in,
                              void* d_out, int out_size)
{
    const float* u    = (const float*)d_in[0];   // [N, 8]
    const float* grid = (const float*)d_in[1];   // [8, ninc+1]
    // d_in[2] = inc  (unused: reconstructed from grid, bit-exact)
    // d_in[3] = ninc (derived from sizes)

    const int n    = in_sizes[0] / NDIM;
    const int gw   = in_sizes[1] / NDIM;         // ninc + 1
    const int ninc = gw - 1;

    float* x    = (float*)d_out;                 // [N, 8]
    float* logj = (float*)d_out + (size_t)n * NDIM;

    const int smem = NDIM * gw * (int)sizeof(float);

    int blocks = BLOCKS;
    if (blocks * THREADS > n) blocks = (n + THREADS - 1) / THREADS;

    vegas_map_kernel<<<blocks, THREADS, smem>>>(
        (const float4*)u, grid, (float4*)x, logj, n, ninc);
}

// round 9
// speedup vs baseline: 1.1003x; 1.1003x over previous
#include <cuda_runtime.h>
#include <math.h>

#define NDIM 8
#define THREADS 256
#define BLOCKS (148 * 6)

// Two points per thread per loop trip: 4 independent LDG.128 issued up front
// (MLP_p1 = 4) before any dependent compute. Grid table staged in SMEM.
template <int NINC_T>
__global__ void __launch_bounds__(THREADS)
vegas_map_kernel(const float4* __restrict__ u4,
                 const float*  __restrict__ grid,
                 float4*       __restrict__ x4,
                 float*        __restrict__ logj,
                 int n, int ninc_rt)
{
    const int ninc = (NINC_T > 0) ? NINC_T : ninc_rt;
    const int gw   = ninc + 1;

    extern __shared__ float sg[];                       // NDIM * gw floats
    for (int i = threadIdx.x; i < NDIM * gw; i += blockDim.x)
        sg[i] = grid[i];
    __syncthreads();

    const float fninc = (float)ninc;
    const float logC  = (float)NDIM * logf(fninc);

    const int stride = gridDim.x * blockDim.x * 2;
    for (int p0 = blockIdx.x * blockDim.x * 2 + threadIdx.x; p0 < n; p0 += stride) {
        const int p1 = p0 + blockDim.x;
        const bool has1 = (p1 < n);

        // ---- front-loaded independent loads (4x LDG.128) ----
        float4 a0 = u4[2 * p0];
        float4 b0 = u4[2 * p0 + 1];
        float4 a1, b1;
        if (has1) { a1 = u4[2 * p1]; b1 = u4[2 * p1 + 1]; }

        float uu0[NDIM] = {a0.x, a0.y, a0.z, a0.w, b0.x, b0.y, b0.z, b0.w};
        float uu1[NDIM] = {a1.x, a1.y, a1.z, a1.w, b1.x, b1.y, b1.z, b1.w};
        float xx0[NDIM], xx1[NDIM];
        float prod0 = 1.0f, prod1 = 1.0f;

        #pragma unroll
        for (int d = 0; d < NDIM; d++) {
            const float* sgd = sg + d * gw;             // immediate offset when NINC_T>0

            float t0  = uu0[d] * fninc;
            int   i0  = (int)t0;                        // u >= 0: trunc == floor
            float du0 = t0 - (float)i0;
            bool  in0 = (i0 < ninc);
            int   c0  = in0 ? i0 : (ninc - 1);
            float g0  = sgd[c0];
            float e0  = sgd[c0 + 1];
            float h0  = e0 - g0;                        // == inc bit-exactly
            xx0[d]    = in0 ? fmaf(h0, du0, g0) : e0;
            prod0    *= h0;

            float t1  = uu1[d] * fninc;
            int   i1  = (int)t1;
            float du1 = t1 - (float)i1;
            bool  in1 = (i1 < ninc);
            int   c1  = in1 ? i1 : (ninc - 1);
            float g1  = sgd[c1];
            float e1  = sgd[c1 + 1];
            float h1  = e1 - g1;
            xx1[d]    = in1 ? fmaf(h1, du1, g1) : e1;
            prod1    *= h1;
        }

        x4[2 * p0]     = make_float4(xx0[0], xx0[1], xx0[2], xx0[3]);
        x4[2 * p0 + 1] = make_float4(xx0[4], xx0[5], xx0[6], xx0[7]);
        logj[p0] = __logf(prod0) + logC;

        if (has1) {
            x4[2 * p1]     = make_float4(xx1[0], xx1[1], xx1[2], xx1[3]);
            x4[2 * p1 + 1] = make_float4(xx1[4], xx1[5], xx1[6], xx1[7]);
            logj[p1] = __logf(prod1) + logC;
        }
    }
}

extern "C" void kernel_launch(void* const* d_in, const int* in_sizes, int n_in,
                              void* d_out, int out_size)
{
    const float* u    = (const float*)d_in[0];   // [N, 8]
    const float* grid = (const float*)d_in[1];   // [8, ninc+1]
    // d_in[2] = inc  (unused: reconstructed from grid, bit-exact)

    const int n    = in_sizes[0] / NDIM;
    const int gw   = in_sizes[1] / NDIM;         // ninc + 1
    const int ninc = gw - 1;

    float* x    = (float*)d_out;                 // [N, 8]
    float* logj = (float*)d_out + (size_t)n * NDIM;

    const int smem = NDIM * gw * (int)sizeof(float);

    int blocks = BLOCKS;
    if (blocks * THREADS * 2 > n) blocks = (n + THREADS * 2 - 1) / (THREADS * 2);

    if (ninc == 1000) {
        vegas_map_kernel<1000><<<blocks, THREADS, smem>>>(
            (const float4*)u, grid, (float4*)x, logj, n, ninc);
    } else {
        vegas_map_kernel<0><<<blocks, THREADS, smem>>>(
            (const float4*)u, grid, (float4*)x, logj, n, ninc);
    }
}

// round 16
// speedup vs baseline: 1.1946x; 1.0857x over previous
#include <cuda_runtime.h>
#include <math.h>

#define NDIM 8
#define THREADS 256
#define CTAS_PER_SM 7
#define BLOCKS (148 * CTAS_PER_SM)

// ILP2 with low register pressure: 4 independent LDG.128 issued up front
// (MLP on the global-latency chain), then point0 is fully computed and stored
// before point1's compute — peak live regs ~28, fits 7 CTAs/SM (36-reg budget).
template <int NINC_T>
__global__ void __launch_bounds__(THREADS, CTAS_PER_SM)
vegas_map_kernel(const float4* __restrict__ u4,
                 const float*  __restrict__ grid,
                 float4*       __restrict__ x4,
                 float*        __restrict__ logj,
                 int n, int ninc_rt)
{
    const int ninc = (NINC_T > 0) ? NINC_T : ninc_rt;
    const int gw   = ninc + 1;

    extern __shared__ float sg[];                       // NDIM * gw floats
    for (int i = threadIdx.x; i < NDIM * gw; i += blockDim.x)
        sg[i] = grid[i];
    __syncthreads();

    const float fninc = (float)ninc;
    const float logC  = (float)NDIM * logf(fninc);

    const int stride = gridDim.x * blockDim.x * 2;
    for (int p0 = blockIdx.x * blockDim.x * 2 + threadIdx.x; p0 < n; p0 += stride) {
        const int p1 = p0 + blockDim.x;
        const bool has1 = (p1 < n);

        // ---- 4 independent global loads issued before any dependent compute ----
        float4 a0 = u4[2 * p0];
        float4 b0 = u4[2 * p0 + 1];
        float4 a1 = has1 ? u4[2 * p1]     : a0;
        float4 b1 = has1 ? u4[2 * p1 + 1] : b0;

        // ---- point 0: compute + store completely, then point 1 ----
        {
            float uu[NDIM] = {a0.x, a0.y, a0.z, a0.w, b0.x, b0.y, b0.z, b0.w};
            float xx[NDIM];
            float prod = 1.0f;
            #pragma unroll
            for (int d = 0; d < NDIM; d++) {
                const float* sgd = sg + d * gw;
                float t  = uu[d] * fninc;
                int   iu = (int)t;                      // u >= 0: trunc == floor
                float du = t - (float)iu;
                bool  in = (iu < ninc);
                int   ic = in ? iu : (ninc - 1);
                float g  = sgd[ic];
                float e  = sgd[ic + 1];
                float h  = e - g;                       // == inc bit-exactly
                xx[d] = in ? fmaf(h, du, g) : e;
                prod *= h;
            }
            x4[2 * p0]     = make_float4(xx[0], xx[1], xx[2], xx[3]);
            x4[2 * p0 + 1] = make_float4(xx[4], xx[5], xx[6], xx[7]);
            logj[p0] = __logf(prod) + logC;
        }

        if (has1) {
            float uu[NDIM] = {a1.x, a1.y, a1.z, a1.w, b1.x, b1.y, b1.z, b1.w};
            float xx[NDIM];
            float prod = 1.0f;
            #pragma unroll
            for (int d = 0; d < NDIM; d++) {
                const float* sgd = sg + d * gw;
                float t  = uu[d] * fninc;
                int   iu = (int)t;
                float du = t - (float)iu;
                bool  in = (iu < ninc);
                int   ic = in ? iu : (ninc - 1);
                float g  = sgd[ic];
                float e  = sgd[ic + 1];
                float h  = e - g;
                xx[d] = in ? fmaf(h, du, g) : e;
                prod *= h;
            }
            x4[2 * p1]     = make_float4(xx[0], xx[1], xx[2], xx[3]);
            x4[2 * p1 + 1] = make_float4(xx[4], xx[5], xx[6], xx[7]);
            logj[p1] = __logf(prod) + logC;
        }
    }
}

extern "C" void kernel_launch(void* const* d_in, const int* in_sizes, int n_in,
                              void* d_out, int out_size)
{
    const float* u    = (const float*)d_in[0];   // [N, 8]
    const float* grid = (const float*)d_in[1];   // [8, ninc+1]
    // d_in[2] = inc  (unused: reconstructed from grid, bit-exact)

    const int n    = in_sizes[0] / NDIM;
    const int gw   = in_sizes[1] / NDIM;         // ninc + 1
    const int ninc = gw - 1;

    float* x    = (float*)d_out;                 // [N, 8]
    float* logj = (float*)d_out + (size_t)n * NDIM;

    const int smem = NDIM * gw * (int)sizeof(float);

    int blocks = BLOCKS;
    if (blocks * THREADS * 2 > n) blocks = (n + THREADS * 2 - 1) / (THREADS * 2);

    if (ninc == 1000) {
        vegas_map_kernel<1000><<<blocks, THREADS, smem>>>(
            (const float4*)u, grid, (float4*)x, logj, n, ninc);
    } else {
        vegas_map_kernel<0><<<blocks, THREADS, smem>>>(
            (const float4*)u, grid, (float4*)x, logj, n, ninc);
    }
}

// round 17
// speedup vs baseline: 1.3709x; 1.1475x over previous
#include <cuda_runtime.h>
#include <math.h>

#define NDIM 8
#define THREADS 512
#define CTAS_PER_SM 3
#define BLOCKS (148 * CTAS_PER_SM)

// Packed-edge table: tbl[d][i] = {grid[d][i], grid[d][i+1]} as float2.
// One aligned LDS.64 per dim per point (was 2x LDS.32). 64 KB smem/CTA,
// 3 CTAs/SM (192 KB), 512 threads/CTA -> 48 warps/SM.
// ILP2: 4 independent LDG.128 front-loaded, then sequential per-point compute
// (low live-reg count, no spills at the 40-reg budget).
template <int NINC_T>
__global__ void __launch_bounds__(THREADS, CTAS_PER_SM)
vegas_map_kernel(const float4* __restrict__ u4,
                 const float*  __restrict__ grid,
                 float4*       __restrict__ x4,
                 float*        __restrict__ logj,
                 int n, int ninc_rt)
{
    const int ninc = (NINC_T > 0) ? NINC_T : ninc_rt;

    extern __shared__ float2 sg2[];                     // NDIM * ninc float2
    for (int idx = threadIdx.x; idx < NDIM * ninc; idx += blockDim.x) {
        const int d = (NINC_T > 0) ? (idx / NINC_T) : (idx / ninc);
        const int i = (NINC_T > 0) ? (idx % NINC_T) : (idx % ninc);
        const float* gd = grid + d * (ninc + 1) + i;
        sg2[idx] = make_float2(gd[0], gd[1]);
    }
    __syncthreads();

    const float fninc = (float)ninc;
    const float logC  = (float)NDIM * logf(fninc);

    const int stride = gridDim.x * blockDim.x * 2;
    for (int p0 = blockIdx.x * blockDim.x * 2 + threadIdx.x; p0 < n; p0 += stride) {
        const int p1 = p0 + blockDim.x;
        const bool has1 = (p1 < n);

        // ---- 4 independent global loads before any dependent compute ----
        float4 a0 = u4[2 * p0];
        float4 b0 = u4[2 * p0 + 1];
        float4 a1 = has1 ? u4[2 * p1]     : a0;
        float4 b1 = has1 ? u4[2 * p1 + 1] : b0;

        // ---- point 0 ----
        {
            float uu[NDIM] = {a0.x, a0.y, a0.z, a0.w, b0.x, b0.y, b0.z, b0.w};
            float xx[NDIM];
            float prod = 1.0f;
            #pragma unroll
            for (int d = 0; d < NDIM; d++) {
                const float2* td = sg2 + d * ninc;
                float t  = uu[d] * fninc;
                int   iu = (int)t;                      // u >= 0: trunc == floor
                float du = t - (float)iu;
                bool  in = (iu < ninc);
                int   ic = in ? iu : (ninc - 1);
                float2 ge = td[ic];                     // {grid[ic], grid[ic+1]} in one LDS.64
                float h  = ge.y - ge.x;                 // == inc bit-exactly
                xx[d] = in ? fmaf(h, du, ge.x) : ge.y;
                prod *= h;
            }
            x4[2 * p0]     = make_float4(xx[0], xx[1], xx[2], xx[3]);
            x4[2 * p0 + 1] = make_float4(xx[4], xx[5], xx[6], xx[7]);
            logj[p0] = __logf(prod) + logC;
        }

        // ---- point 1 ----
        if (has1) {
            float uu[NDIM] = {a1.x, a1.y, a1.z, a1.w, b1.x, b1.y, b1.z, b1.w};
            float xx[NDIM];
            float prod = 1.0f;
            #pragma unroll
            for (int d = 0; d < NDIM; d++) {
                const float2* td = sg2 + d * ninc;
                float t  = uu[d] * fninc;
                int   iu = (int)t;
                float du = t - (float)iu;
                bool  in = (iu < ninc);
                int   ic = in ? iu : (ninc - 1);
                float2 ge = td[ic];
                float h  = ge.y - ge.x;
                xx[d] = in ? fmaf(h, du, ge.x) : ge.y;
                prod *= h;
            }
            x4[2 * p1]     = make_float4(xx[0], xx[1], xx[2], xx[3]);
            x4[2 * p1 + 1] = make_float4(xx[4], xx[5], xx[6], xx[7]);
            logj[p1] = __logf(prod) + logC;
        }
    }
}

extern "C" void kernel_launch(void* const* d_in, const int* in_sizes, int n_in,
                              void* d_out, int out_size)
{
    const float* u    = (const float*)d_in[0];   // [N, 8]
    const float* grid = (const float*)d_in[1];   // [8, ninc+1]
    // d_in[2] = inc  (unused: reconstructed from grid, bit-exact)

    const int n    = in_sizes[0] / NDIM;
    const int gw   = in_sizes[1] / NDIM;         // ninc + 1
    const int ninc = gw - 1;

    float* x    = (float*)d_out;                 // [N, 8]
    float* logj = (float*)d_out + (size_t)n * NDIM;

    const int smem = NDIM * ninc * (int)sizeof(float2);   // 64 KB for ninc=1000

    int blocks = BLOCKS;
    if (blocks * THREADS * 2 > n) blocks = (n + THREADS * 2 - 1) / (THREADS * 2);

    if (ninc == 1000) {
        cudaFuncSetAttribute(vegas_map_kernel<1000>,
                             cudaFuncAttributeMaxDynamicSharedMemorySize, smem);
        vegas_map_kernel<1000><<<blocks, THREADS, smem>>>(
            (const float4*)u, grid, (float4*)x, logj, n, ninc);
    } else {
        cudaFuncSetAttribute(vegas_map_kernel<0>,
                             cudaFuncAttributeMaxDynamicSharedMemorySize, smem);
        vegas_map_kernel<0><<<blocks, THREADS, smem>>>(
            (const float4*)u, grid, (float4*)x, logj, n, ninc);
    }
}